// round 17
// baseline (speedup 1.0000x reference)
#include <cuda_runtime.h>
#include <cuda_bf16.h>
#include <math.h>

#define Nn 50000
#define Ee 800000
#define Hh 8
#define Dd 128

// ---------------- scratch (static device globals; no runtime alloc) ----------------
__device__ int   g_is64;
__device__ int   g_eidx[2 * Ee];
__device__ int   g_rowcnt[Nn];
__device__ int   g_cursor[Nn];
__device__ int   g_rowptr[Nn + 1];
__device__ int   g_bsum[64];
__device__ int   g_boff[64];
__device__ int   g_ssrc[Ee];
__device__ float g_sw[Ee];
__device__ float g_Wh0[Nn * Dd];
__device__ float g_es[Nn * Hh];
__device__ float g_ed[Nn * Hh];
__device__ float g_att[Ee * Hh];                // logits, then unnormalized z
__device__ float g_inv[Nn * Hh];                // per (node, head) 1/sum(z)
__device__ float g_x1[Nn * Dd];                 // GAT layer-0 output (post-ELU)
__device__ __nv_bfloat16 g_xh[Nn * Dd];         // split input x (hi/lo)
__device__ __nv_bfloat16 g_xl[Nn * Dd];
__device__ __nv_bfloat16 g_x2h[Nn * Dd];        // split GCN layer-1 output
__device__ __nv_bfloat16 g_x2l[Nn * Dd];
__device__ __nv_bfloat16 g_yh[Nn * 1024];       // split aggregated x1 (per head)
__device__ __nv_bfloat16 g_yl[Nn * 1024];
__device__ __nv_bfloat16 g_Bth[128 * 1024];     // W1 packed [n][k]
__device__ __nv_bfloat16 g_Btl[128 * 1024];
__device__ __nv_bfloat16 g_B0h[128 * 128];      // W0 packed [n][k]
__device__ __nv_bfloat16 g_B0l[128 * 128];
__device__ __nv_bfloat16 g_Bg0h[128 * 128];     // gcn_W0 packed [n][k]
__device__ __nv_bfloat16 g_Bg0l[128 * 128];
__device__ __nv_bfloat16 g_Bg1h[128 * 128];     // gcn_W1 packed [n][k]
__device__ __nv_bfloat16 g_Bg1l[128 * 128];
__device__ float g_hg[Nn * Dd];
__device__ float g_x2b[Nn * Dd];
__device__ float g_u1[Hh * Dd];
__device__ float g_v1[Hh * Dd];

// ---------------- base-target PTX helpers (sm_80+ features only) ----------------
__device__ __forceinline__ unsigned s2u(const void* p) {
    unsigned a;
    asm("{ .reg .u64 t; cvta.to.shared.u64 t, %1; cvt.u32.u64 %0, t; }" : "=r"(a) : "l"(p));
    return a;
}
__device__ __forceinline__ void cpa16(unsigned dst, const void* src, int szsrc) {
    asm volatile("cp.async.cg.shared.global [%0], [%1], 16, %2;"
                 :: "r"(dst), "l"(src), "r"(szsrc) : "memory");
}
__device__ __forceinline__ void cpa_commit() {
    asm volatile("cp.async.commit_group;" ::: "memory");
}
template <int N>
__device__ __forceinline__ void cpa_wait() {
    asm volatile("cp.async.wait_group %0;" :: "n"(N) : "memory");
}
__device__ __forceinline__ void ldmx4(unsigned* r, unsigned addr) {
    asm volatile("ldmatrix.sync.aligned.m8n8.x4.shared.b16 {%0,%1,%2,%3}, [%4];"
                 : "=r"(r[0]), "=r"(r[1]), "=r"(r[2]), "=r"(r[3]) : "r"(addr));
}
__device__ __forceinline__ void ldmx2(unsigned* r, unsigned addr) {
    asm volatile("ldmatrix.sync.aligned.m8n8.x2.shared.b16 {%0,%1}, [%2];"
                 : "=r"(r[0]), "=r"(r[1]) : "r"(addr));
}
__device__ __forceinline__ void mma16816(float* c, const unsigned* a, const unsigned* b) {
    asm volatile(
        "mma.sync.aligned.m16n8k16.row.col.f32.bf16.bf16.f32 "
        "{%0,%1,%2,%3}, {%4,%5,%6,%7}, {%8,%9}, {%0,%1,%2,%3};"
        : "+f"(c[0]), "+f"(c[1]), "+f"(c[2]), "+f"(c[3])
        : "r"(a[0]), "r"(a[1]), "r"(a[2]), "r"(a[3]), "r"(b[0]), "r"(b[1]));
}
__device__ __forceinline__ void bsplit(float v, __nv_bfloat16& hi, __nv_bfloat16& lo) {
    hi = __float2bfloat16(v);
    lo = __float2bfloat16(v - __bfloat162float(hi));
}

// ---------------- edge-index dtype detection ----------------
__global__ void k_detect(const int* __restrict__ ei32) {
    if (threadIdx.x == 0 && blockIdx.x == 0) {
        int is64 = 1;
        for (int i = 0; i < 256; i++)
            if (ei32[2 * i + 1] != 0) { is64 = 0; break; }
        g_is64 = is64;
    }
}

// ---------------- CSR build ----------------
__global__ void k_zero() {
    int i = blockIdx.x * blockDim.x + threadIdx.x;
    if (i < Nn) { g_rowcnt[i] = 0; g_cursor[i] = 0; }
}
__global__ void k_convcnt(const int* __restrict__ ei32) {
    int i = blockIdx.x * blockDim.x + threadIdx.x;
    if (i >= Ee) return;
    int s = g_is64 ? ei32[2 * i] : ei32[i];
    int d = g_is64 ? ei32[2 * (Ee + i)] : ei32[Ee + i];
    g_eidx[i] = s;
    g_eidx[Ee + i] = d;
    atomicAdd(&g_rowcnt[d], 1);
}
__global__ void k_scan1() {
    __shared__ int tmp[1024];
    int b = blockIdx.x, t = threadIdx.x;
    int i = b * 1024 + t;
    tmp[t] = (i < Nn) ? g_rowcnt[i] : 0;
    __syncthreads();
    for (int d = 1; d < 1024; d <<= 1) {
        int add = (t >= d) ? tmp[t - d] : 0;
        __syncthreads();
        tmp[t] += add;
        __syncthreads();
    }
    if (i < Nn) g_rowptr[i + 1] = tmp[t];
    if (t == 1023) g_bsum[b] = tmp[1023];
}
__global__ void k_scan2() {
    __shared__ int tmp[64];
    int t = threadIdx.x;
    const int nb = (Nn + 1023) / 1024;
    tmp[t] = (t < nb) ? g_bsum[t] : 0;
    __syncthreads();
    for (int d = 1; d < 64; d <<= 1) {
        int add = (t >= d) ? tmp[t - d] : 0;
        __syncthreads();
        tmp[t] += add;
        __syncthreads();
    }
    g_boff[t] = (t == 0) ? 0 : tmp[t - 1];
}
__global__ void k_scan3() {
    int b = blockIdx.x, t = threadIdx.x;
    int i = b * 1024 + t;
    if (i < Nn) g_rowptr[i + 1] += g_boff[b];
    if (b == 0 && t == 0) g_rowptr[0] = 0;
}
__global__ void k_scatter(const float* __restrict__ w) {
    int i = blockIdx.x * blockDim.x + threadIdx.x;
    if (i >= Ee) return;
    int s = g_eidx[i];
    int d = g_eidx[Ee + i];
    int p = g_rowptr[d] + atomicAdd(&g_cursor[d], 1);
    g_ssrc[p] = s;
    g_sw[p]   = w[i];
}
__global__ void k_normw() {
    __shared__ float red[128];
    int r = blockIdx.x, t = threadIdx.x;
    int p0 = g_rowptr[r], p1 = g_rowptr[r + 1];
    float ds = 0.f;
    for (int p = p0 + t; p < p1; p += 128) ds += g_sw[p];
    red[t] = ds;
    __syncthreads();
    for (int d = 64; d > 0; d >>= 1) {
        if (t < d) red[t] += red[t + d];
        __syncthreads();
    }
    float inv = 1.f / fmaxf(red[0], 1e-16f);
    for (int p = p0 + t; p < p1; p += 128) g_sw[p] *= inv;
}

// ---------------- input split + weight packs ----------------
__global__ void k_splitx(const float* __restrict__ x) {
    int i = blockIdx.x * blockDim.x + threadIdx.x;
    if (i >= Nn * Dd) return;
    bsplit(x[i], g_xh[i], g_xl[i]);
}
__global__ void k_packWsplit(const float* __restrict__ W,
                             __nv_bfloat16* __restrict__ Bh, __nv_bfloat16* __restrict__ Bl) {
    int i = blockIdx.x * blockDim.x + threadIdx.x;
    if (i >= 128 * 128) return;
    int n = i >> 7, k = i & 127;
    bsplit(W[k * 128 + n], Bh[i], Bl[i]);
}
__global__ void k_packW0split(const float* __restrict__ W0) {
    int i = blockIdx.x * blockDim.x + threadIdx.x;
    if (i >= 128 * 128) return;
    int n = i >> 7, k = i & 127;
    int h = n >> 4, f = n & 15;
    bsplit(W0[h * (Dd * 16) + k * 16 + f], g_B0h[i], g_B0l[i]);
}
__global__ void k_packW1(const float* __restrict__ W1) {
    int i = blockIdx.x * blockDim.x + threadIdx.x;
    if (i >= 128 * 1024) return;
    int n = i >> 10, k = i & 1023;
    int h = k >> 7, kk = k & 127;
    bsplit(W1[h * (Dd * Dd) + kk * Dd + n], g_Bth[i], g_Btl[i]);
}
__global__ void k_uv1(const float* __restrict__ W1,
                      const float* __restrict__ a_s, const float* __restrict__ a_d) {
    int i = blockIdx.x * blockDim.x + threadIdx.x;
    if (i >= Hh * Dd) return;
    int h = i >> 7, k = i & 127;
    const float* w = &W1[h * Dd * Dd + k * Dd];
    float su = 0.f, sv = 0.f;
    #pragma unroll 8
    for (int f = 0; f < Dd; f++) {
        float v = __ldg(&w[f]);
        su = fmaf(v, __ldg(&a_s[h * Dd + f]), su);
        sv = fmaf(v, __ldg(&a_d[h * Dd + f]), sv);
    }
    g_u1[i] = su; g_v1[i] = sv;
}

// ---------------- es / ed ----------------
__global__ void k_esed0(const float* __restrict__ a_s, const float* __restrict__ a_d) {
    int i = blockIdx.x * blockDim.x + threadIdx.x;
    if (i >= Nn * Hh) return;
    int n = i >> 3, h = i & 7;
    const float* w = &g_Wh0[n * Dd + h * 16];
    float s = 0.f, d = 0.f;
    #pragma unroll
    for (int f = 0; f < 16; f++) {
        float v = w[f];
        s = fmaf(v, __ldg(&a_s[h * 16 + f]), s);
        d = fmaf(v, __ldg(&a_d[h * 16 + f]), d);
    }
    g_es[i] = s; g_ed[i] = d;
}
__global__ __launch_bounds__(512) void k_esed1() {
    __shared__ float su[1024], sv[1024];
    int t = threadIdx.x;
    for (int i = t; i < 1024; i += 512) { su[i] = g_u1[i]; sv[i] = g_v1[i]; }
    __syncthreads();
    int w = blockIdx.x * 16 + (t >> 5);
    if (w >= Nn) return;
    int lane = t & 31;
    float4 xv = *(const float4*)&g_x1[w * Dd + lane * 4];
    #pragma unroll
    for (int h = 0; h < 8; h++) {
        const float* u = &su[h * 128 + lane * 4];
        const float* v = &sv[h * 128 + lane * 4];
        float s = xv.x * u[0] + xv.y * u[1] + xv.z * u[2] + xv.w * u[3];
        float d = xv.x * v[0] + xv.y * v[1] + xv.z * v[2] + xv.w * v[3];
        #pragma unroll
        for (int o = 16; o; o >>= 1) {
            s += __shfl_xor_sync(0xffffffffu, s, o);
            d += __shfl_xor_sync(0xffffffffu, d, o);
        }
        if (lane == 0) { g_es[w * 8 + h] = s; g_ed[w * 8 + h] = d; }
    }
}

// ---------------- attention: 2 passes, ONE exp per edge-head ----------------
// p1: gather logits (store), running max. p2: z=exp(l-m) stored; inv stored in g_inv.
// Normalization (×inv) is deferred into the aggregation kernels.
__global__ void k_att() {
    int wid  = (blockIdx.x * blockDim.x + threadIdx.x) >> 5;
    int lane = threadIdx.x & 31;
    if (wid >= Nn) return;
    int p0 = g_rowptr[wid], p1 = g_rowptr[wid + 1];
    int deg = p1 - p0;
    if (deg == 0) return;
    int h = lane & 7;
    float edv = g_ed[wid * 8 + h];
    int tot = deg * 8;
    float m = -1e30f;
    for (int i = lane; i < tot; i += 32) {
        int e = i >> 3;
        float x = g_es[g_ssrc[p0 + e] * 8 + h] + edv;
        x = x > 0.f ? x : 0.2f * x;
        g_att[(p0 + e) * 8 + h] = x;
        m = fmaxf(m, x);
    }
    m = fmaxf(m, __shfl_xor_sync(0xffffffffu, m, 8));
    m = fmaxf(m, __shfl_xor_sync(0xffffffffu, m, 16));
    float s = 0.f;
    for (int i = lane; i < tot; i += 32) {
        int idx = (p0 + (i >> 3)) * 8 + h;
        float z = __expf(g_att[idx] - m);
        g_att[idx] = z;
        s += z;
    }
    s += __shfl_xor_sync(0xffffffffu, s, 8);
    s += __shfl_xor_sync(0xffffffffu, s, 16);
    if (lane < 8) g_inv[wid * 8 + lane] = 1.f / fmaxf(s, 1e-16f);
}

// ---------------- aggregations (block per dst row, no atomics) ----------------
__global__ void k_agg_gat0() {
    int r = blockIdx.x, t = threadIdx.x;
    int p0 = g_rowptr[r], p1 = g_rowptr[r + 1];
    int h = t >> 4;
    float acc = 0.f;
    #pragma unroll 4
    for (int p = p0; p < p1; p++)
        acc = fmaf(g_att[p * 8 + h], g_Wh0[g_ssrc[p] * Dd + t], acc);
    float iv = (p1 > p0) ? g_inv[r * 8 + h] : 0.f;
    acc *= iv;
    g_x1[r * Dd + t] = acc > 0.f ? acc : expm1f(acc);
}
__global__ void k_agg_gat1() {
    int r = blockIdx.x, t = threadIdx.x;
    int p0 = g_rowptr[r], p1 = g_rowptr[r + 1];
    float acc[8] = {0.f, 0.f, 0.f, 0.f, 0.f, 0.f, 0.f, 0.f};
    for (int p = p0; p < p1; p++) {
        float v = g_x1[g_ssrc[p] * Dd + t];
        float4 a0 = *(const float4*)&g_att[p * 8];
        float4 a1 = *(const float4*)&g_att[p * 8 + 4];
        acc[0] = fmaf(a0.x, v, acc[0]); acc[1] = fmaf(a0.y, v, acc[1]);
        acc[2] = fmaf(a0.z, v, acc[2]); acc[3] = fmaf(a0.w, v, acc[3]);
        acc[4] = fmaf(a1.x, v, acc[4]); acc[5] = fmaf(a1.y, v, acc[5]);
        acc[6] = fmaf(a1.z, v, acc[6]); acc[7] = fmaf(a1.w, v, acc[7]);
    }
    int base = r * 1024 + t;
    if (p1 > p0) {
        float4 i0 = *(const float4*)&g_inv[r * 8];
        float4 i1 = *(const float4*)&g_inv[r * 8 + 4];
        acc[0] *= i0.x; acc[1] *= i0.y; acc[2] *= i0.z; acc[3] *= i0.w;
        acc[4] *= i1.x; acc[5] *= i1.y; acc[6] *= i1.z; acc[7] *= i1.w;
    }
    #pragma unroll
    for (int h = 0; h < 8; h++)
        bsplit(acc[h], g_yh[base + h * Dd], g_yl[base + h * Dd]);
}
__global__ void k_agg_gcn(const float* __restrict__ hsrc, float* __restrict__ out,
                          __nv_bfloat16* __restrict__ oh, __nv_bfloat16* __restrict__ ol,
                          int wsplit) {
    int r = blockIdx.x, t = threadIdx.x;
    int p0 = g_rowptr[r], p1 = g_rowptr[r + 1];
    float acc = 0.f;
    #pragma unroll 4
    for (int p = p0; p < p1; p++)
        acc = fmaf(g_sw[p], hsrc[g_ssrc[p] * Dd + t], acc);
    float v = fmaxf(acc, 0.f);
    if (wsplit) bsplit(v, oh[r * Dd + t], ol[r * Dd + t]);
    else        out[r * Dd + t] = v;
}

// ---------------- mma.sync split-bf16 GEMM: C[M,128] = alpha * A @ B^T ----------------
#define TCH 64
#define PITCHB 144
#define TILE_BYTES (128 * PITCHB)
#define BUF_BYTES (4 * TILE_BYTES)

extern "C" __global__ __launch_bounds__(256, 1) void gemm_tc(
    const __nv_bfloat16* __restrict__ Ah, const __nv_bfloat16* __restrict__ Al,
    const __nv_bfloat16* __restrict__ Bh, const __nv_bfloat16* __restrict__ Bl,
    float* __restrict__ C, const float* __restrict__ Cmax, float alpha, int M, int Kel)
{
    extern __shared__ char smem[];
    const unsigned sbase = s2u(smem);
    const int tid  = threadIdx.x;
    const int wid  = tid >> 5;
    const int lane = tid & 31;
    const int row0 = blockIdx.x * 128;
    const int mw = wid & 1, nw = wid >> 1;
    const int m0 = mw * 64, n0 = nw * 32;
    const int NCH = Kel >> 6;

    const __nv_bfloat16* srcs[4] = { Ah, Al, Bh, Bl };

    auto load_chunk = [&](int c, int buf) {
        unsigned bb = sbase + buf * BUF_BYTES;
        #pragma unroll
        for (int i = 0; i < 16; i++) {
            int o   = tid + 256 * i;
            int tl  = o >> 10;
            int r   = (o & 1023) >> 3;
            int seg = o & 7;
            unsigned dst = bb + tl * TILE_BYTES + r * PITCHB + seg * 16;
            size_t goff = (size_t)c * TCH + seg * 8;
            const __nv_bfloat16* s;
            int ok = 16;
            if (tl < 2) {
                int gr = row0 + r;
                s = srcs[tl] + (size_t)gr * Kel + goff;
                if (gr >= M) ok = 0;
            } else {
                s = srcs[tl] + (size_t)r * Kel + goff;
            }
            cpa16(dst, s, ok);
        }
        cpa_commit();
    };

    float acc[4][4][4] = {};

    load_chunk(0, 0);

    for (int c = 0; c < NCH; c++) {
        int buf = c & 1;
        if (c + 1 < NCH) { load_chunk(c + 1, buf ^ 1); cpa_wait<1>(); }
        else             { cpa_wait<0>(); }
        __syncthreads();

        unsigned bb  = sbase + buf * BUF_BYTES;
        unsigned uAh = bb;
        unsigned uAl = bb + TILE_BYTES;
        unsigned uBh = bb + 2 * TILE_BYTES;
        unsigned uBl = bb + 3 * TILE_BYTES;

        int l15 = lane & 15;
        #pragma unroll
        for (int ks = 0; ks < 4; ks++) {
            unsigned ah[4][4], al[4][4], bh[4][2], bl[4][2];
            unsigned aoff = (unsigned)(m0 + l15) * PITCHB + ks * 32 + (lane >> 4) * 16;
            #pragma unroll
            for (int i = 0; i < 4; i++) {
                ldmx4(ah[i], uAh + aoff + i * 16 * PITCHB);
                ldmx4(al[i], uAl + aoff + i * 16 * PITCHB);
            }
            unsigned boff = (unsigned)(n0 + (l15 & 7)) * PITCHB + ks * 32 + (l15 >> 3) * 16;
            #pragma unroll
            for (int j = 0; j < 4; j++) {
                ldmx2(bh[j], uBh + boff + j * 8 * PITCHB);
                ldmx2(bl[j], uBl + boff + j * 8 * PITCHB);
            }
            #pragma unroll
            for (int i = 0; i < 4; i++)
                #pragma unroll
                for (int j = 0; j < 4; j++) {
                    mma16816(acc[i][j], ah[i], bh[j]);
                    mma16816(acc[i][j], ah[i], bl[j]);
                    mma16816(acc[i][j], al[i], bh[j]);
                }
        }
        __syncthreads();
    }

    int rb = row0 + m0 + (lane >> 2);
    int cb = n0 + (lane & 3) * 2;
    #pragma unroll
    for (int i = 0; i < 4; i++) {
        #pragma unroll
        for (int j = 0; j < 4; j++) {
            int r1 = rb + i * 16, c1 = cb + j * 8;
            if (r1 < M) {
                float2 v = make_float2(acc[i][j][0] * alpha, acc[i][j][1] * alpha);
                if (Cmax) {
                    float2 m2 = *(const float2*)&Cmax[(size_t)r1 * 128 + c1];
                    v.x = fmaxf(v.x, m2.x); v.y = fmaxf(v.y, m2.y);
                }
                *(float2*)&C[(size_t)r1 * 128 + c1] = v;
            }
            int r2 = r1 + 8;
            if (r2 < M) {
                float2 v = make_float2(acc[i][j][2] * alpha, acc[i][j][3] * alpha);
                if (Cmax) {
                    float2 m2 = *(const float2*)&Cmax[(size_t)r2 * 128 + c1];
                    v.x = fmaxf(v.x, m2.x); v.y = fmaxf(v.y, m2.y);
                }
                *(float2*)&C[(size_t)r2 * 128 + c1] = v;
            }
        }
    }
}

// ---------------- launch ----------------
extern "C" void kernel_launch(void* const* d_in, const int* in_sizes, int n_in,
                              void* d_out, int out_size) {
    const float* x   = (const float*)d_in[0];
    const int*   ei  = (const int*)d_in[1];
    const float* ew  = (const float*)d_in[2];
    const float* W0  = (const float*)d_in[3];
    const float* a0s = (const float*)d_in[4];
    const float* a0d = (const float*)d_in[5];
    const float* W1  = (const float*)d_in[6];
    const float* a1s = (const float*)d_in[7];
    const float* a1d = (const float*)d_in[8];
    const float* gW0 = (const float*)d_in[9];
    const float* gW1 = (const float*)d_in[10];
    float* out = (float*)d_out;

    float *pWh0, *pHg, *pX2b;
    __nv_bfloat16 *pYh, *pYl, *pXh, *pXl, *pX2h, *pX2l;
    __nv_bfloat16 *pBth, *pBtl, *pB0h, *pB0l, *pBg0h, *pBg0l, *pBg1h, *pBg1l;
    cudaGetSymbolAddress((void**)&pWh0,  g_Wh0);
    cudaGetSymbolAddress((void**)&pHg,   g_hg);
    cudaGetSymbolAddress((void**)&pX2b,  g_x2b);
    cudaGetSymbolAddress((void**)&pYh,   g_yh);
    cudaGetSymbolAddress((void**)&pYl,   g_yl);
    cudaGetSymbolAddress((void**)&pXh,   g_xh);
    cudaGetSymbolAddress((void**)&pXl,   g_xl);
    cudaGetSymbolAddress((void**)&pX2h,  g_x2h);
    cudaGetSymbolAddress((void**)&pX2l,  g_x2l);
    cudaGetSymbolAddress((void**)&pBth,  g_Bth);
    cudaGetSymbolAddress((void**)&pBtl,  g_Btl);
    cudaGetSymbolAddress((void**)&pB0h,  g_B0h);
    cudaGetSymbolAddress((void**)&pB0l,  g_B0l);
    cudaGetSymbolAddress((void**)&pBg0h, g_Bg0h);
    cudaGetSymbolAddress((void**)&pBg0l, g_Bg0l);
    cudaGetSymbolAddress((void**)&pBg1h, g_Bg1h);
    cudaGetSymbolAddress((void**)&pBg1l, g_Bg1l);

    const int gA = (Nn + 127) / 128;
    const int gS = (Nn + 1023) / 1024;   // 49
    const int SMEM_TC = 2 * BUF_BYTES;   // 147456 bytes
    cudaFuncSetAttribute(gemm_tc, cudaFuncAttributeMaxDynamicSharedMemorySize, SMEM_TC);

    // edge-index normalization + CSR build (parallel scan)
    k_detect <<<1, 32>>>(ei);
    k_zero   <<<(Nn + 255) / 256, 256>>>();
    k_convcnt<<<(Ee + 255) / 256, 256>>>(ei);
    k_scan1  <<<gS, 1024>>>();
    k_scan2  <<<1, 64>>>();
    k_scan3  <<<gS, 1024>>>();
    k_scatter<<<(Ee + 255) / 256, 256>>>(ew);
    k_normw  <<<Nn, 128>>>();

    // input split + weight packs
    k_splitx    <<<(Nn * Dd + 255) / 256, 256>>>(x);
    k_packW0split<<<(128 * 128 + 255) / 256, 256>>>(W0);
    k_packWsplit<<<(128 * 128 + 255) / 256, 256>>>(gW0, pBg0h, pBg0l);
    k_packWsplit<<<(128 * 128 + 255) / 256, 256>>>(gW1, pBg1h, pBg1l);
    k_packW1    <<<(128 * 1024 + 255) / 256, 256>>>(W1);

    // GAT layer 0
    gemm_tc  <<<gA, 256, SMEM_TC>>>(pXh, pXl, pB0h, pB0l, pWh0, (const float*)0, 1.f, Nn, 128);
    k_esed0  <<<(Nn * Hh + 255) / 256, 256>>>(a0s, a0d);
    k_att    <<<(Nn + 7) / 8, 256>>>();
    k_agg_gat0<<<Nn, 128>>>();

    // GCN layer 0
    gemm_tc  <<<gA, 256, SMEM_TC>>>(pXh, pXl, pBg0h, pBg0l, pHg, (const float*)0, 1.f, Nn, 128);
    k_agg_gcn<<<Nn, 128>>>(pHg, (float*)0, pX2h, pX2l, 1);

    // GCN layer 1 (before GAT-L1 GEMM so the final max fuses into its epilogue)
    gemm_tc  <<<gA, 256, SMEM_TC>>>(pX2h, pX2l, pBg1h, pBg1l, pHg, (const float*)0, 1.f, Nn, 128);
    k_agg_gcn<<<Nn, 128>>>(pHg, pX2b, (__nv_bfloat16*)0, (__nv_bfloat16*)0, 0);

    // GAT layer 1: aggregate (split-bf16), then tensor GEMM with fused max(out, x2b)
    k_uv1    <<<4, 256>>>(W1, a1s, a1d);
    k_esed1  <<<(Nn + 15) / 16, 512>>>();
    k_att    <<<(Nn + 7) / 8, 256>>>();
    k_agg_gat1<<<Nn, 128>>>();
    gemm_tc  <<<gA, 256, SMEM_TC>>>(pYh, pYl, pBth, pBtl, out, pX2b, 0.125f, Nn, 1024);
}